// round 17
// baseline (speedup 1.0000x reference)
#include <cuda_runtime.h>
#include <cuda_fp16.h>
#include <cstdint>

// ---------------- problem constants ----------------------------------------
#define Bq     16
#define NSEQ   1569            // 1 + 8*196
#define DMODEL 768
#define NH     12
#define DH     64
#define NF     8
#define NPF    196
#define MROWS  (Bq * NSEQ)     // 25104
#define QKVC   (3 * DMODEL)    // 2304
#define QKH_W  (2 * DMODEL)    // 1536 (Q|K fp16 buffer width)

// scratch (no cudaMalloc allowed)
__device__ __half g_qkh[(size_t)MROWS * QKH_W];     // Q|K fp16 (qkv epilogue)
__device__ float  g_v[(size_t)MROWS * DMODEL];      // V fp32, tf32-rounded
__device__ __half g_attnh[(size_t)MROWS * DMODEL];  // attention out, fp16
__device__ __half g_xh[(size_t)MROWS * DMODEL];     // x, fp16
__device__ __half g_wqh[(size_t)QKVC * DMODEL];     // w_qkv^T [N][K] fp16
__device__ __half g_wph[(size_t)DMODEL * DMODEL];   // w_proj^T [N][K] fp16
__device__ float  g_cls[192 * 8 * 65];              // cls split-k partials

__device__ __forceinline__ uint32_t f2tf(float x) {
    uint32_t r;
    asm("cvt.rna.tf32.f32 %0, %1;" : "=r"(r) : "f"(x));
    return r;
}
__device__ __forceinline__ float f2tff(float x) { return __uint_as_float(f2tf(x)); }

__device__ __forceinline__ uint32_t s2u(const void* p) {
    return (uint32_t)__cvta_generic_to_shared(p);
}

#define MMA_TF32(c, a0,a1,a2,a3, b0,b1)                                          \
    asm volatile(                                                                 \
        "mma.sync.aligned.m16n8k8.row.col.f32.tf32.tf32.f32 "                     \
        "{%0,%1,%2,%3}, {%4,%5,%6,%7}, {%8,%9}, {%0,%1,%2,%3};"                   \
        : "+f"(c[0]), "+f"(c[1]), "+f"(c[2]), "+f"(c[3])                          \
        : "r"(a0), "r"(a1), "r"(a2), "r"(a3), "r"(b0), "r"(b1))

#define MMA_F16(c, a0,a1,a2,a3, b0,b1)                                           \
    asm volatile(                                                                 \
        "mma.sync.aligned.m16n8k16.row.col.f32.f16.f16.f32 "                      \
        "{%0,%1,%2,%3}, {%4,%5,%6,%7}, {%8,%9}, {%0,%1,%2,%3};"                   \
        : "+f"(c[0]), "+f"(c[1]), "+f"(c[2]), "+f"(c[3])                          \
        : "r"(a0), "r"(a1), "r"(a2), "r"(a3), "r"(b0), "r"(b1))

// ---------------- prep: x fp32 -> fp16 --------------------------------------
#define N4X ((MROWS * DMODEL) / 4)

__global__ __launch_bounds__(256) void prep_x(
    const float* __restrict__ in, __half* __restrict__ out)
{
    int i = blockIdx.x * 256 + threadIdx.x;
    if (i < N4X) {
        float4 v = reinterpret_cast<const float4*>(in)[i];
        __half2* op = reinterpret_cast<__half2*>(out) + i * 2;
        op[0] = __floats2half2_rn(v.x, v.y);
        op[1] = __floats2half2_rn(v.z, v.w);
    }
}

// ---------------- prep: transpose fp32 [R][C] -> fp16 [C][R] ----------------
__global__ __launch_bounds__(256) void transpose_h(
    const float* __restrict__ in, __half* __restrict__ out, int R, int C)
{
    __shared__ float t[32][33];
    const int bx = blockIdx.x * 32;
    const int by = blockIdx.y * 32;
    const int tx = threadIdx.x & 31, ty = threadIdx.x >> 5;
#pragma unroll
    for (int j = 0; j < 4; j++)
        t[ty + j * 8][tx] = in[(long)(by + ty + j * 8) * C + bx + tx];
    __syncthreads();
#pragma unroll
    for (int j = 0; j < 4; j++)
        out[(long)(bx + ty + j * 8) * R + by + tx] = __float2half(t[tx][ty + j * 8]);
}

// ---------------- FP16 GEMM v2: 64x64 warp tiles, 1 CTA/SM ------------------
// CTA tile 128x256, 8 warps (2 along M x 4 along N), each warp 64x64.
// Halves smem-crossbar bytes per MMA (128B/MMA vs 192B/MMA) -- the measured
// binding resource of the previous GEMM.
#define BM 128
#define BN 256
#define HSTR 36                 // u32 per row (144 B: conflict-free frags)
#define ABUF (128 * HSTR)
#define BBUF (256 * HSTR)
#define STAGES 3
#define GEMM_SMEM (STAGES * (ABUF + BBUF) * 4)   // 165888 bytes

template <int OUTM>   // 0: proj (fp32+bias), 1: qkv split (QK fp16 | V fp32)
__global__ __launch_bounds__(256, 1) void gemm_f16(
    const __half* __restrict__ A, const __half* __restrict__ Bt,
    const float* __restrict__ bias, float* __restrict__ Cf,
    __half* __restrict__ qkh, float* __restrict__ vout,
    int Mr, int Nc, int Kd)
{
    extern __shared__ uint32_t smu[];
    uint32_t* As = smu;
    uint32_t* Bs = smu + STAGES * ABUF;

    const int tid  = threadIdx.x;
    const int warp = tid >> 5, lane = tid & 31;
    const int gid  = lane >> 2, tig = lane & 3;
    const int wm   = (warp >> 2) * 64;    // 2 warps along M
    const int wn   = (warp & 3) * 64;     // 4 warps along N
    const int brow = blockIdx.y * BM;
    const int bcol = blockIdx.x * BN;

    float acc[4][8][4];
#pragma unroll
    for (int mi = 0; mi < 4; mi++)
#pragma unroll
        for (int ni = 0; ni < 8; ni++)
#pragma unroll
            for (int r = 0; r < 4; r++) acc[mi][ni][r] = 0.f;

    const int nkt = Kd / 64;

    auto issue = [&](int kt) {
        const int buf = kt % STAGES;
        uint32_t* Ab = As + buf * ABUF;
        uint32_t* Bb = Bs + buf * BBUF;
#pragma unroll
        for (int i = 0; i < 4; i++) {
            int cid = tid + i * 256;      // 1024 chunks of 16B
            int row = cid >> 3, c16 = cid & 7;
            const __half* src = A + (long)(brow + row) * Kd + kt * 64 + c16 * 8;
            int sz = (brow + row < Mr) ? 16 : 0;
            asm volatile("cp.async.cg.shared.global [%0], [%1], 16, %2;"
                         :: "r"(s2u(Ab + row * HSTR + c16 * 4)), "l"(src), "r"(sz));
        }
#pragma unroll
        for (int i = 0; i < 8; i++) {
            int cid = tid + i * 256;      // 2048 chunks
            int row = cid >> 3, c16 = cid & 7;
            const __half* src = Bt + (long)(bcol + row) * Kd + kt * 64 + c16 * 8;
            asm volatile("cp.async.cg.shared.global [%0], [%1], 16;"
                         :: "r"(s2u(Bb + row * HSTR + c16 * 4)), "l"(src));
        }
    };

    auto compute = [&](int buf) {
        const uint32_t* Ab = As + buf * ABUF;
        const uint32_t* Bb = Bs + buf * BBUF;
#pragma unroll
        for (int ks = 0; ks < 4; ks++) {
            const int k0 = ks * 8;
            uint32_t af[4][4], bf[8][2];
#pragma unroll
            for (int mi = 0; mi < 4; mi++) {
                const uint32_t* p = Ab + (wm + mi * 16 + gid) * HSTR + k0 + tig;
                af[mi][0] = p[0];
                af[mi][1] = p[8 * HSTR];
                af[mi][2] = p[4];
                af[mi][3] = p[8 * HSTR + 4];
            }
#pragma unroll
            for (int ni = 0; ni < 8; ni++) {
                const uint32_t* p = Bb + (wn + ni * 8 + gid) * HSTR + k0 + tig;
                bf[ni][0] = p[0];
                bf[ni][1] = p[4];
            }
#pragma unroll
            for (int mi = 0; mi < 4; mi++)
#pragma unroll
                for (int ni = 0; ni < 8; ni++)
                    MMA_F16(acc[mi][ni], af[mi][0], af[mi][1], af[mi][2], af[mi][3],
                            bf[ni][0], bf[ni][1]);
        }
    };

#pragma unroll
    for (int s = 0; s < STAGES - 1; s++) {
        issue(s);
        asm volatile("cp.async.commit_group;");
    }

#pragma unroll 1
    for (int kt = 0; kt < nkt; kt++) {
        asm volatile("cp.async.wait_group %0;" :: "n"(STAGES - 2));
        __syncthreads();
        compute(kt % STAGES);
        if (kt + STAGES - 1 < nkt) issue(kt + STAGES - 1);
        asm volatile("cp.async.commit_group;");
    }

    const bool toV = (OUTM == 1) && (bcol >= QKH_W);   // block-uniform (1536=6*256)
#pragma unroll
    for (int mi = 0; mi < 4; mi++) {
        int r0 = brow + wm + mi * 16 + gid;
#pragma unroll
        for (int ni = 0; ni < 8; ni++) {
            int c0 = bcol + wn + ni * 8 + tig * 2;
#pragma unroll
            for (int hh = 0; hh < 2; hh++) {
                int rr = r0 + hh * 8;
                if (rr >= Mr) continue;
                float v0 = acc[mi][ni][2 * hh];
                float v1 = acc[mi][ni][2 * hh + 1];
                if (OUTM == 0) {
                    v0 += bias[c0]; v1 += bias[c0 + 1];
                    *reinterpret_cast<float2*>(Cf + (long)rr * Nc + c0) =
                        make_float2(v0, v1);
                } else if (toV) {
                    *reinterpret_cast<float2*>(vout + (long)rr * DMODEL + c0 - QKH_W) =
                        make_float2(f2tff(v0), f2tff(v1));
                } else {
                    *reinterpret_cast<__half2*>(qkh + (long)rr * QKH_W + c0) =
                        __floats2half2_rn(v0, v1);
                }
            }
        }
    }
}

// ---------------- frame attention v5: fp16 S-phase, tf32 O-phase ------------
#define KSTRU 36
#define VSTR  72
#define F_SMEM ((200 * KSTRU + 200 * VSTR) * 4)   // 86400 bytes

__global__ __launch_bounds__(256, 2) void frame_attn_mma(
    const __half* __restrict__ qkh, const float* __restrict__ vsrc,
    __half* __restrict__ attn)
{
    extern __shared__ uint32_t smu[];
    uint32_t* Kh = smu;
    float*    Vs = reinterpret_cast<float*>(smu + 200 * KSTRU);

    const int tid  = threadIdx.x;
    const int warp = tid >> 5, lane = tid & 31;
    const int gid  = lane >> 2, tig = lane & 3;

    const int bid2 = blockIdx.x;
    const int half = bid2 & 1;
    const int bid  = bid2 >> 1;
    const int fr   = bid & 7;
    const int h    = (bid >> 3) % NH;
    const int b    = bid / (NF * NH);

    const int tbase  = half * 7;
    const int ntiles = half ? 6 : 7;

    const long rowbase = (long)b * NSEQ;
    const int  hoff    = h * DH;

    const uint32_t* Vu = reinterpret_cast<const uint32_t*>(Vs);

    for (int idx = tid; idx < 200 * 16; idx += 256) {
        int j  = idx >> 4;
        int c4 = (idx & 15) << 2;
        int t  = (j == 0) ? 0 : (1 + fr * NPF + j - 1);
        const float* src = (j < 197)
            ? vsrc + (rowbase + t) * DMODEL + hoff + c4
            : vsrc;
        int sz = (j < 197) ? 16 : 0;
        asm volatile("cp.async.cg.shared.global [%0], [%1], 16, %2;"
                     :: "r"(s2u(Vs + j * VSTR + c4)), "l"(src), "r"(sz));
    }
    asm volatile("cp.async.commit_group;");

    const int nrows = ntiles * 16;
    const __half2 hs = __float2half2_rn(0.125f);
    for (int idx = tid; idx < nrows * 8; idx += 256) {
        int row = idx >> 3;
        int c8  = idx & 7;
        int grow = tbase * 16 + row;
        uint4 v = make_uint4(0u, 0u, 0u, 0u);
        if (grow < NPF) {
            const uint4* qp = reinterpret_cast<const uint4*>(
                qkh + (rowbase + 1 + fr * NPF + grow) * QKH_W + hoff) + c8;
            uint4 u = *qp;
            __half2 h0 = __hmul2(*reinterpret_cast<__half2*>(&u.x), hs);
            __half2 h1 = __hmul2(*reinterpret_cast<__half2*>(&u.y), hs);
            __half2 h2 = __hmul2(*reinterpret_cast<__half2*>(&u.z), hs);
            __half2 h3 = __hmul2(*reinterpret_cast<__half2*>(&u.w), hs);
            v.x = *reinterpret_cast<uint32_t*>(&h0);
            v.y = *reinterpret_cast<uint32_t*>(&h1);
            v.z = *reinterpret_cast<uint32_t*>(&h2);
            v.w = *reinterpret_cast<uint32_t*>(&h3);
        }
        *reinterpret_cast<uint4*>(Kh + row * KSTRU + c8 * 4) = v;
    }
    __syncthreads();

    uint32_t af[4][4];
    if (warp < ntiles) {
        const int r0 = warp * 16 + gid;
#pragma unroll
        for (int kc = 0; kc < 4; kc++) {
            int c0 = kc * 8 + tig;
            af[kc][0] = Kh[r0 * KSTRU + c0];
            af[kc][1] = Kh[(r0 + 8) * KSTRU + c0];
            af[kc][2] = Kh[r0 * KSTRU + c0 + 4];
            af[kc][3] = Kh[(r0 + 8) * KSTRU + c0 + 4];
        }
    }
    __syncthreads();

    for (int idx = tid; idx < 200 * 8; idx += 256) {
        int j   = idx >> 3;
        int c16 = idx & 7;
        int t   = (j == 0) ? 0 : (1 + fr * NPF + j - 1);
        const __half* src = (j < 197)
            ? qkh + (rowbase + t) * QKH_W + DMODEL + hoff + c16 * 8
            : qkh;
        int sz = (j < 197) ? 16 : 0;
        asm volatile("cp.async.cg.shared.global [%0], [%1], 16, %2;"
                     :: "r"(s2u(Kh + j * KSTRU + c16 * 4)), "l"(src), "r"(sz));
    }
    asm volatile("cp.async.commit_group;");
    asm volatile("cp.async.wait_group 0;");
    __syncthreads();

    if (warp < ntiles) {
        const int tile = tbase + warp;

        float o[8][4];
#pragma unroll
        for (int dt = 0; dt < 8; dt++)
#pragma unroll
            for (int r = 0; r < 4; r++) o[dt][r] = 0.f;
        float rs0 = 0.f, rs1 = 0.f;

        const int src0 = (lane & ~3) | (tig >> 1);
        const int src1 = src0 + 2;
        const bool oddt = (tig & 1);

#pragma unroll
        for (int chunk = 0; chunk < 5; chunk++) {
            float c[5][4];
#pragma unroll
            for (int ntl = 0; ntl < 5; ntl++)
#pragma unroll
                for (int r = 0; r < 4; r++) c[ntl][r] = 0.f;

#pragma unroll
            for (int ntl = 0; ntl < 5; ntl++) {
                const int nt = chunk * 5 + ntl;
                const uint32_t* kb = Kh + (nt * 8 + gid) * KSTRU + tig;
#pragma unroll
                for (int kc = 0; kc < 4; kc++) {
                    uint32_t b0 = kb[kc * 8];
                    uint32_t b1 = kb[kc * 8 + 4];
                    MMA_F16(c[ntl], af[kc][0], af[kc][1], af[kc][2], af[kc][3],
                            b0, b1);
                }
            }

#pragma unroll
            for (int ntl = 0; ntl < 5; ntl++) {
                const int j0 = (chunk * 5 + ntl) * 8 + tig * 2;
                float p0 = (j0     < 197) ? __expf(c[ntl][0]) : 0.f;
                float p1 = (j0 + 1 < 197) ? __expf(c[ntl][1]) : 0.f;
                float p2 = (j0     < 197) ? __expf(c[ntl][2]) : 0.f;
                float p3 = (j0 + 1 < 197) ? __expf(c[ntl][3]) : 0.f;
                rs0 += p0 + p1;
                rs1 += p2 + p3;
                c[ntl][0] = __uint_as_float(f2tf(p0));
                c[ntl][1] = __uint_as_float(f2tf(p1));
                c[ntl][2] = __uint_as_float(f2tf(p2));
                c[ntl][3] = __uint_as_float(f2tf(p3));
            }

#pragma unroll
            for (int ntl = 0; ntl < 5; ntl++) {
                const int nt = chunk * 5 + ntl;
                float x0 = __shfl_sync(0xffffffffu, c[ntl][0], src0);
                float x1 = __shfl_sync(0xffffffffu, c[ntl][1], src0);
                float x2 = __shfl_sync(0xffffffffu, c[ntl][2], src0);
                float x3 = __shfl_sync(0xffffffffu, c[ntl][3], src0);
                float y0 = __shfl_sync(0xffffffffu, c[ntl][0], src1);
                float y1 = __shfl_sync(0xffffffffu, c[ntl][1], src1);
                float y2 = __shfl_sync(0xffffffffu, c[ntl][2], src1);
                float y3 = __shfl_sync(0xffffffffu, c[ntl][3], src1);
                uint32_t a0 = __float_as_uint(oddt ? x1 : x0);
                uint32_t a1 = __float_as_uint(oddt ? x3 : x2);
                uint32_t a2 = __float_as_uint(oddt ? y1 : y0);
                uint32_t a3 = __float_as_uint(oddt ? y3 : y2);
                const uint32_t* vb = Vu + (nt * 8 + tig) * VSTR + gid;
#pragma unroll
                for (int dt = 0; dt < 8; dt++) {
                    uint32_t b0 = vb[dt * 8];
                    uint32_t b1 = vb[4 * VSTR + dt * 8];
                    MMA_TF32(o[dt], a0, a1, a2, a3, b0, b1);
                }
            }
        }

        rs0 += __shfl_xor_sync(0xffffffffu, rs0, 1);
        rs0 += __shfl_xor_sync(0xffffffffu, rs0, 2);
        rs1 += __shfl_xor_sync(0xffffffffu, rs1, 1);
        rs1 += __shfl_xor_sync(0xffffffffu, rs1, 2);
        const float inv0 = 1.f / rs0;
        const float inv1 = 1.f / rs1;

#pragma unroll
        for (int hh = 0; hh < 2; hh++) {
            int row = tile * 16 + gid + hh * 8;
            if (row < NPF) {
                float inv = hh ? inv1 : inv0;
                __half2* op = reinterpret_cast<__half2*>(
                    attn + (rowbase + 1 + fr * NPF + row) * DMODEL + hoff);
#pragma unroll
                for (int dt = 0; dt < 8; dt++)
                    op[dt * 4 + tig] = __floats2half2_rn(
                        o[dt][2 * hh] * inv, o[dt][2 * hh + 1] * inv);
            }
        }
    }
}

// ---------------- cls attention: split-K phase 1 ----------------------------
#define CLS_CH 197

__global__ __launch_bounds__(256) void cls_p1(
    const __half* __restrict__ qkh, const float* __restrict__ vsrc,
    float* __restrict__ part)
{
    const int blk  = blockIdx.x;
    const int c    = blk & 7;
    const int bh   = blk >> 3;
    const int b    = bh / NH;
    const int h    = bh % NH;
    const int tid  = threadIdx.x;
    const int warp = tid >> 5, lane = tid & 31;

    __shared__ float qs[64];
    __shared__ float wacc[8][64];
    __shared__ float wl[8];

    const long rowbase = (long)b * NSEQ;
    const int  hoff    = h * DH;

    if (tid < 64)
        qs[tid] = __half2float(qkh[rowbase * QKH_W + hoff + tid]) * 0.125f;
    __syncthreads();

    const int j0 = c * CLS_CH;
    const int jn = (j0 + CLS_CH <= NSEQ) ? CLS_CH : (NSEQ - j0);

    const float q0 = qs[lane * 2];
    const float q1 = qs[lane * 2 + 1];

    float a0 = 0.f, a1 = 0.f, l = 0.f;

    for (int jj = warp; jj < jn; jj += 8) {
        const long r = rowbase + j0 + jj;
        __half2 kk = *reinterpret_cast<const __half2*>(
            qkh + r * QKH_W + DMODEL + hoff + lane * 2);
        float2 kf = __half22float2(kk);
        float s = q0 * kf.x + q1 * kf.y;
#pragma unroll
        for (int off = 16; off; off >>= 1)
            s += __shfl_xor_sync(0xffffffffu, s, off);
        float p = __expf(s);
        l += p;
        float2 vv = *reinterpret_cast<const float2*>(
            vsrc + r * DMODEL + hoff + lane * 2);
        a0 = fmaf(p, vv.x, a0);
        a1 = fmaf(p, vv.y, a1);
    }

    wacc[warp][lane * 2]     = a0;
    wacc[warp][lane * 2 + 1] = a1;
    if (lane == 0) wl[warp] = l;
    __syncthreads();

    if (tid < 64) {
        float s = 0.f;
#pragma unroll
        for (int w = 0; w < 8; w++) s += wacc[w][tid];
        part[(size_t)blk * 65 + tid] = s;
        if (tid == 0) {
            float lt = 0.f;
#pragma unroll
            for (int w = 0; w < 8; w++) lt += wl[w];
            part[(size_t)blk * 65 + 64] = lt;
        }
    }
}

// ---------------- cls attention: split-K phase 2 ----------------------------
__global__ __launch_bounds__(64) void cls_p2(
    const float* __restrict__ part, __half* __restrict__ attn)
{
    const int bh = blockIdx.x;
    const int b  = bh / NH;
    const int h  = bh % NH;
    const int d  = threadIdx.x;

    float s = 0.f, lt = 0.f;
#pragma unroll
    for (int c = 0; c < 8; c++) {
        s  += part[(size_t)(bh * 8 + c) * 65 + d];
        lt += part[(size_t)(bh * 8 + c) * 65 + 64];
    }
    attn[(long)b * NSEQ * DMODEL + h * DH + d] = __float2half(s / lt);
}

// ---------------- host launch ----------------------------------------------
extern "C" void kernel_launch(void* const* d_in, const int* in_sizes, int n_in,
                              void* d_out, int out_size)
{
    const float* x      = (const float*)d_in[0];
    const float* w_qkv  = (const float*)d_in[1];
    const float* w_proj = (const float*)d_in[2];
    const float* b_proj = (const float*)d_in[3];
    float* out = (float*)d_out;

    float *vbuf, *clsp;
    __half *qkh, *attnh, *xh, *wqh, *wph;
    cudaGetSymbolAddress((void**)&qkh,   g_qkh);
    cudaGetSymbolAddress((void**)&vbuf,  g_v);
    cudaGetSymbolAddress((void**)&attnh, g_attnh);
    cudaGetSymbolAddress((void**)&xh,    g_xh);
    cudaGetSymbolAddress((void**)&wqh,   g_wqh);
    cudaGetSymbolAddress((void**)&wph,   g_wph);
    cudaGetSymbolAddress((void**)&clsp,  g_cls);

    cudaFuncSetAttribute((const void*)gemm_f16<0>,
                         cudaFuncAttributeMaxDynamicSharedMemorySize, GEMM_SMEM);
    cudaFuncSetAttribute((const void*)gemm_f16<1>,
                         cudaFuncAttributeMaxDynamicSharedMemorySize, GEMM_SMEM);
    cudaFuncSetAttribute(frame_attn_mma,
                         cudaFuncAttributeMaxDynamicSharedMemorySize, F_SMEM);

    // prep
    prep_x<<<(N4X + 255) / 256, 256>>>(x, xh);
    transpose_h<<<dim3(QKVC / 32, DMODEL / 32), 256>>>(w_qkv, wqh, DMODEL, QKVC);
    transpose_h<<<dim3(DMODEL / 32, DMODEL / 32), 256>>>(w_proj, wph, DMODEL, DMODEL);

    const int mtiles = (MROWS + BM - 1) / BM;   // 197

    // qkv GEMM: split epilogue (Q,K fp16; V fp32 tf32-rounded)
    gemm_f16<1><<<dim3(QKVC / BN, mtiles), 256, GEMM_SMEM>>>(
        xh, wqh, nullptr, nullptr, qkh, vbuf, MROWS, QKVC, DMODEL);

    cls_p1<<<Bq * NH * 8, 256>>>(qkh, vbuf, clsp);
    frame_attn_mma<<<Bq * NH * NF * 2, 256, F_SMEM>>>(qkh, vbuf, attnh);
    cls_p2<<<Bq * NH, 64>>>(clsp, attnh);

    // proj GEMM: fp32 out + bias
    gemm_f16<0><<<dim3(DMODEL / BN, mtiles), 256, GEMM_SMEM>>>(
        attnh, wph, b_proj, out, nullptr, nullptr, MROWS, DMODEL, DMODEL);
}